// round 3
// baseline (speedup 1.0000x reference)
#include <cuda_runtime.h>

#define S_DIM 128
#define N_DIM 256
#define C_DIM 256
#define H_DIM 8
#define D_H   32
#define P_DIM 128
#define R_TOT (S_DIM * N_DIM)     // 32768 rows
#define QKV_K 768
#define SCALE_F 0.17677669529663687f
#define NEG_F  (-1000000000.0f)
#define EPS_F  1e-5f

// Scratch (allocation-free rule: __device__ globals)
__device__ float g_qkv[(size_t)R_TOT * QKV_K];          // 96 MB: fused q|k|v rows
__device__ float g_bias[(size_t)H_DIM * N_DIM * N_DIM]; // 2 MB: pair bias [h][n][m]
__device__ float g_att[(size_t)R_TOT * C_DIM];          // 32 MB: attention output
__device__ float g_z[(size_t)R_TOT * C_DIM];            // 32 MB: pre-LN residual sum
__device__ float g_maskf[S_DIM * N_DIM];                // canonical 0/1 mask

// ---------------------------------------------------------------------------
// Kernel 0: mask canonicalization. Detects storage dtype of the bool mask
// (uint8 / int32 / float32) from raw byte patterns, expands to float 0/1.
//   uint8 bool : nonzero bytes appear at p%4==1 (and everywhere)
//   int32 0/1  : nonzero bytes ONLY at p%4==0 (little-endian LSB)
//   float 0/1f : nonzero bytes ONLY at p%4 in {2,3} (1.0f = 00 00 80 3F)
// Deterministic, single block, negligible cost.
// ---------------------------------------------------------------------------
__global__ void k_mask(const void* __restrict__ mraw) {
    __shared__ int cnt[3];                // [p%4==0] [p%4==1] [p%4 in {2,3}]
    const unsigned char* b = (const unsigned char*)mraw;
    const int tid = threadIdx.x;
    if (tid < 3) cnt[tid] = 0;
    __syncthreads();
    int l0 = 0, l1 = 0, l23 = 0;
    for (int i = tid * 16; i < tid * 16 + 16; i++) {   // first 4096 bytes
        int nz = (b[i] != 0);
        int p = i & 3;
        if (p == 0) l0 += nz;
        else if (p == 1) l1 += nz;
        else l23 += nz;
    }
    atomicAdd(&cnt[0], l0);
    atomicAdd(&cnt[1], l1);
    atomicAdd(&cnt[2], l23);
    __syncthreads();
    int mode;
    if (cnt[1] > 0) mode = 0;             // uint8 bool
    else if (cnt[0] > 0) mode = 1;        // int32
    else mode = 2;                        // float32
    for (int i = tid; i < S_DIM * N_DIM; i += 256) {
        float v;
        if (mode == 0)      v = (float)b[i];
        else if (mode == 1) v = (float)((const int*)mraw)[i];
        else                v = ((const float*)mraw)[i];
        g_maskf[i] = (v != 0.0f) ? 1.0f : 0.0f;
    }
}

// ---------------------------------------------------------------------------
// Kernel 1: qkv = msa @ qkv_w^T + qkv_b.   A: 32768x256, W: 768x256 (row-major)
// Tile 128(M) x 64(N), K-step 16, 256 threads, 8x4 micro-tile per thread.
// ---------------------------------------------------------------------------
__global__ void __launch_bounds__(256) k_qkv(const float* __restrict__ A,
                                             const float* __restrict__ W,
                                             const float* __restrict__ bias) {
    __shared__ float As[16][132];   // As[k][m], 132*4=528B row stride (16B-mult)
    __shared__ float Bs[16][68];    // Bs[k][n], 68*4=272B row stride (16B-mult)
    const int tid = threadIdx.x;
    const int bm = blockIdx.y * 128;
    const int bn = blockIdx.x * 64;
    const int tx = tid & 15, ty = tid >> 4;
    const int row0 = ty * 8, col0 = tx * 4;

    float acc[8][4];
#pragma unroll
    for (int i = 0; i < 8; i++)
#pragma unroll
        for (int j = 0; j < 4; j++) acc[i][j] = 0.f;

    for (int kt = 0; kt < 256; kt += 16) {
#pragma unroll
        for (int j = 0; j < 2; j++) {            // A tile: 128x16 = 512 float4s
            int chunk = tid + j * 256;
            int r = chunk >> 2, kc = (chunk & 3) << 2;
            float4 v = *(const float4*)(A + (size_t)(bm + r) * 256 + kt + kc);
            As[kc + 0][r] = v.x; As[kc + 1][r] = v.y;
            As[kc + 2][r] = v.z; As[kc + 3][r] = v.w;
        }
        {                                        // W tile: 64x16 = 256 float4s
            int n = tid >> 2, kc = (tid & 3) << 2;
            float4 v = *(const float4*)(W + (size_t)(bn + n) * 256 + kt + kc);
            Bs[kc + 0][n] = v.x; Bs[kc + 1][n] = v.y;
            Bs[kc + 2][n] = v.z; Bs[kc + 3][n] = v.w;
        }
        __syncthreads();
#pragma unroll
        for (int k = 0; k < 16; k++) {
            float4 a0 = *(const float4*)&As[k][row0];
            float4 a1 = *(const float4*)&As[k][row0 + 4];
            float4 b0 = *(const float4*)&Bs[k][col0];
            float av[8] = {a0.x, a0.y, a0.z, a0.w, a1.x, a1.y, a1.z, a1.w};
            float bv[4] = {b0.x, b0.y, b0.z, b0.w};
#pragma unroll
            for (int i = 0; i < 8; i++)
#pragma unroll
                for (int j = 0; j < 4; j++) acc[i][j] += av[i] * bv[j];
        }
        __syncthreads();
    }

#pragma unroll
    for (int i = 0; i < 8; i++) {
        int jj = bn + col0;
        float4 o;
        o.x = acc[i][0] + bias[jj + 0];
        o.y = acc[i][1] + bias[jj + 1];
        o.z = acc[i][2] + bias[jj + 2];
        o.w = acc[i][3] + bias[jj + 3];
        *(float4*)(g_qkv + (size_t)(bm + row0 + i) * QKV_K + jj) = o;
    }
}

// ---------------------------------------------------------------------------
// Kernel 2: pair bias.  bias[h][n][m] = dot(pair[n][m][:], pb_w[h][:]) + pb_b[h]
// One block = 32 (n,m) rows, 256 threads: thread = (row, h).
// ---------------------------------------------------------------------------
__global__ void __launch_bounds__(256) k_pair(const float* __restrict__ pair,
                                              const float* __restrict__ pw,
                                              const float* __restrict__ pb) {
    __shared__ float pr[32][128];
    __shared__ float ws[8 * 128];
    const int tid = threadIdx.x;
    const int rb = blockIdx.x * 32;

    ((float4*)ws)[tid] = ((const float4*)pw)[tid];   // 8*128 floats = 256 float4
#pragma unroll
    for (int j = 0; j < 4; j++) {                    // 32*128 floats = 1024 float4
        int chunk = tid + j * 256;
        int r = chunk >> 5, pc = (chunk & 31) << 2;
        *(float4*)&pr[r][pc] = *(const float4*)(pair + (size_t)(rb + r) * 128 + pc);
    }
    __syncthreads();

    const int r = tid >> 3, h = tid & 7;
    const float* wr = ws + h * 128;
    float s = 0.f;
#pragma unroll
    for (int p = 0; p < 128; p += 4) {
        float4 a = *(const float4*)&pr[r][p];
        float4 w = *(const float4*)(wr + p);
        s += a.x * w.x + a.y * w.y + a.z * w.z + a.w * w.w;
    }
    g_bias[(size_t)h * (N_DIM * N_DIM) + rb + r] = s + pb[h];
}

// ---------------------------------------------------------------------------
// Kernel 3: attention. One CTA per (s,h). K,V resident in smem, 8 query chunks
// of 32. Scores stored TRANSPOSED sc[m][n] (stride 33, conflict-free) which is
// exactly the A^T layout the PV GEMM consumes. Unnormalized exp + 1/sum scale.
// ---------------------------------------------------------------------------
#define ATT_SMEM_FLOATS (8192 + 9216 + 8448 + 1024 + 256 + 256 + 256)
#define ATT_SMEM_BYTES  (ATT_SMEM_FLOATS * 4)

__global__ void __launch_bounds__(256) k_attn() {
    extern __shared__ float smf[];
    float* ks   = smf;            // [32][256]  ks[d*256+m]   (K transposed)
    float* vs   = ks + 8192;      // [256][36]  vs[m*36+d]    (V natural, padded)
    float* sc   = vs + 9216;      // [256][33]  sc[m*33+n]    (scores^T, padded)
    float* qs   = sc + 8448;      // [32][32]   qs[d*32+n]    (Q chunk transposed)
    float* pmax = qs + 1024;      // [8][32]
    float* psum = pmax + 256;     // [8][32]
    float* mk   = psum + 256;     // [256]

    const int h = blockIdx.x;
    const int s = blockIdx.y;
    const int tid = threadIdx.x;
    const int lane = tid & 31;
    const int warp = tid >> 5;

    mk[tid] = g_maskf[s * 256 + tid];
    {   // stage K (transposed) and V (natural): row m = tid
        const float* kb = g_qkv + (size_t)(s * 256 + tid) * QKV_K + 256 + h * 32;
        const float* vb = g_qkv + (size_t)(s * 256 + tid) * QKV_K + 512 + h * 32;
#pragma unroll
        for (int d4 = 0; d4 < 8; d4++) {
            float4 v = *(const float4*)(kb + d4 * 4);
            ks[(d4 * 4 + 0) * 256 + tid] = v.x;
            ks[(d4 * 4 + 1) * 256 + tid] = v.y;
            ks[(d4 * 4 + 2) * 256 + tid] = v.z;
            ks[(d4 * 4 + 3) * 256 + tid] = v.w;
            *(float4*)(vs + tid * 36 + d4 * 4) = *(const float4*)(vb + d4 * 4);
        }
    }
    __syncthreads();

    const int tyn = warp;           // score micro-tile: n0 = tyn*4
    const int txm = lane;           // m = txm + j*32  (lane-consecutive -> no conflicts)
    const int pvn = tid >> 3;       // PV mapping: output row n
    const int pvd = (tid & 7) * 4;  // PV mapping: d chunk

    for (int qc = 0; qc < 8; qc++) {
        const int n0g = qc * 32;
        {   // stage Q chunk transposed
            int n = tid >> 3, dc = (tid & 7) << 2;
            float4 v = *(const float4*)(g_qkv + (size_t)(s * 256 + n0g + n) * QKV_K + h * 32 + dc);
            qs[(dc + 0) * 32 + n] = v.x;
            qs[(dc + 1) * 32 + n] = v.y;
            qs[(dc + 2) * 32 + n] = v.z;
            qs[(dc + 3) * 32 + n] = v.w;
        }
        __syncthreads();

        float acc[4][8];
#pragma unroll
        for (int i = 0; i < 4; i++)
#pragma unroll
            for (int j = 0; j < 8; j++) acc[i][j] = 0.f;

#pragma unroll 4
        for (int d = 0; d < 32; d++) {
            float4 q4 = *(const float4*)(qs + d * 32 + tyn * 4);
            float kv[8];
#pragma unroll
            for (int j = 0; j < 8; j++) kv[j] = ks[d * 256 + txm + j * 32];
            float qa[4] = {q4.x, q4.y, q4.z, q4.w};
#pragma unroll
            for (int i = 0; i < 4; i++)
#pragma unroll
                for (int j = 0; j < 8; j++) acc[i][j] += qa[i] * kv[j];
        }

        // mask (BEFORE bias, as in reference), add pair bias, store transposed
#pragma unroll
        for (int i = 0; i < 4; i++) {
            int nl = tyn * 4 + i;
            float mn = mk[n0g + nl];
            const float* brow = g_bias + ((size_t)h * 256 + n0g + nl) * 256;
#pragma unroll
            for (int j = 0; j < 8; j++) {
                int m = txm + j * 32;
                float v = acc[i][j] * SCALE_F;
                if (mn * mk[m] < 0.5f) v = NEG_F;
                v += brow[m];
                sc[m * 33 + nl] = v;
            }
        }
        __syncthreads();

        // softmax pass A: warp owns m in [warp*32, warp*32+32), lane = n
        {
            float lm = -3.4e38f;
#pragma unroll 8
            for (int mm = 0; mm < 32; mm++)
                lm = fmaxf(lm, sc[(warp * 32 + mm) * 33 + lane]);
            pmax[warp * 32 + lane] = lm;
        }
        __syncthreads();
        float rm = -3.4e38f;
#pragma unroll
        for (int sg = 0; sg < 8; sg++) rm = fmaxf(rm, pmax[sg * 32 + lane]);
        float lsum = 0.f;
#pragma unroll 8
        for (int mm = 0; mm < 32; mm++) {
            int m = warp * 32 + mm;
            float e = __expf(sc[m * 33 + lane] - rm);
            sc[m * 33 + lane] = e;
            lsum += e;
        }
        psum[warp * 32 + lane] = lsum;
        __syncthreads();

        // PV: out[n][d] = (1/sum[n]) * sum_m exp[m][n] * v[m][d]
        {
            float ssum = 0.f;
#pragma unroll
            for (int sg = 0; sg < 8; sg++) ssum += psum[sg * 32 + pvn];
            float inv = 1.0f / ssum;
            float ox = 0.f, oy = 0.f, oz = 0.f, ow = 0.f;
#pragma unroll 4
            for (int m = 0; m < 256; m++) {
                float w = sc[m * 33 + pvn];
                float4 v = *(const float4*)(vs + m * 36 + pvd);
                ox += w * v.x; oy += w * v.y; oz += w * v.z; ow += w * v.w;
            }
            float4 o = {ox * inv, oy * inv, oz * inv, ow * inv};
            *(float4*)(g_att + (size_t)(s * 256 + n0g + pvn) * 256 + h * 32 + pvd) = o;
        }
        __syncthreads();
    }
}

// ---------------------------------------------------------------------------
// Kernel 4: out-proj + bias + residual.  z = msa + g_att @ out_w^T + out_b
// Tile 32 rows x 256 cols, full-K A resident in smem, W streamed in K-tiles.
// ---------------------------------------------------------------------------
__global__ void __launch_bounds__(256) k_proj(const float* __restrict__ W,
                                              const float* __restrict__ bias,
                                              const float* __restrict__ msa) {
    __shared__ float As[256 * 32];   // As[k*32 + r]
    __shared__ float Ws[16][264];    // Ws[k][c], 264*4=1056B stride (16B-mult)
    const int tid = threadIdx.x;
    const int bm = blockIdx.x * 32;

    {   // stage full A tile transposed (32 x 256)
        int r = tid >> 3, c0 = (tid & 7) << 5;
        const float* ar = g_att + (size_t)(bm + r) * 256 + c0;
#pragma unroll
        for (int j = 0; j < 8; j++) {
            float4 v = *(const float4*)(ar + j * 4);
            As[(c0 + j * 4 + 0) * 32 + r] = v.x;
            As[(c0 + j * 4 + 1) * 32 + r] = v.y;
            As[(c0 + j * 4 + 2) * 32 + r] = v.z;
            As[(c0 + j * 4 + 3) * 32 + r] = v.w;
        }
    }
    const int txc = tid & 31, tyr = tid >> 5;
    const int c0 = txc * 8, r0 = tyr * 4;

    float acc[4][8];
#pragma unroll
    for (int i = 0; i < 4; i++)
#pragma unroll
        for (int j = 0; j < 8; j++) acc[i][j] = 0.f;

    for (int kt = 0; kt < 256; kt += 16) {
        __syncthreads();   // covers first-iter A staging + Ws reuse
#pragma unroll
        for (int j = 0; j < 4; j++) {    // W tile 256x16 = 1024 float4s
            int chunk = tid + j * 256;
            int c = chunk >> 2, kc = (chunk & 3) << 2;
            float4 v = *(const float4*)(W + (size_t)c * 256 + kt + kc);
            Ws[kc + 0][c] = v.x; Ws[kc + 1][c] = v.y;
            Ws[kc + 2][c] = v.z; Ws[kc + 3][c] = v.w;
        }
        __syncthreads();
#pragma unroll
        for (int k = 0; k < 16; k++) {
            float4 a  = *(const float4*)(As + (kt + k) * 32 + r0);
            float4 w0 = *(const float4*)&Ws[k][c0];
            float4 w1 = *(const float4*)&Ws[k][c0 + 4];
            float av[4] = {a.x, a.y, a.z, a.w};
            float wv[8] = {w0.x, w0.y, w0.z, w0.w, w1.x, w1.y, w1.z, w1.w};
#pragma unroll
            for (int i = 0; i < 4; i++)
#pragma unroll
                for (int j = 0; j < 8; j++) acc[i][j] += av[i] * wv[j];
        }
    }

    float4 bb0 = *(const float4*)(bias + c0);
    float4 bb1 = *(const float4*)(bias + c0 + 4);
#pragma unroll
    for (int i = 0; i < 4; i++) {
        int r = bm + r0 + i;
        const float* mrow = msa + (size_t)r * 256;
        float4 m0 = *(const float4*)(mrow + c0);
        float4 m1 = *(const float4*)(mrow + c0 + 4);
        float4 o0, o1;
        o0.x = acc[i][0] + bb0.x + m0.x; o0.y = acc[i][1] + bb0.y + m0.y;
        o0.z = acc[i][2] + bb0.z + m0.z; o0.w = acc[i][3] + bb0.w + m0.w;
        o1.x = acc[i][4] + bb1.x + m1.x; o1.y = acc[i][5] + bb1.y + m1.y;
        o1.z = acc[i][6] + bb1.z + m1.z; o1.w = acc[i][7] + bb1.w + m1.w;
        *(float4*)(g_z + (size_t)r * 256 + c0)     = o0;
        *(float4*)(g_z + (size_t)r * 256 + c0 + 4) = o1;
    }
}

// ---------------------------------------------------------------------------
// Kernel 5: layernorm over last dim (256). One block per row.
// ---------------------------------------------------------------------------
__global__ void __launch_bounds__(256) k_ln(const float* __restrict__ gamma,
                                            const float* __restrict__ beta,
                                            float* __restrict__ out) {
    __shared__ float red[256];
    const int r = blockIdx.x;
    const int tid = threadIdx.x;
    float x = g_z[(size_t)r * 256 + tid];

    red[tid] = x;
    __syncthreads();
    for (int off = 128; off > 0; off >>= 1) {
        if (tid < off) red[tid] += red[tid + off];
        __syncthreads();
    }
    float mu = red[0] * (1.0f / 256.0f);
    __syncthreads();
    float d = x - mu;
    red[tid] = d * d;
    __syncthreads();
    for (int off = 128; off > 0; off >>= 1) {
        if (tid < off) red[tid] += red[tid + off];
        __syncthreads();
    }
    float var = red[0] * (1.0f / 256.0f);
    float rs = rsqrtf(var + EPS_F);
    out[(size_t)r * 256 + tid] = d * rs * gamma[tid] + beta[tid];
}

// ---------------------------------------------------------------------------
extern "C" void kernel_launch(void* const* d_in, const int* in_sizes, int n_in,
                              void* d_out, int out_size) {
    const float* msa            = (const float*)d_in[0];
    const float* pair           = (const float*)d_in[1];
    const void*  mask_raw       = (const void*)d_in[2];
    const float* qkv_w          = (const float*)d_in[3];
    const float* qkv_b          = (const float*)d_in[4];
    const float* out_w          = (const float*)d_in[5];
    const float* out_b          = (const float*)d_in[6];
    const float* pb_w           = (const float*)d_in[7];
    const float* pb_b           = (const float*)d_in[8];
    const float* gamma          = (const float*)d_in[9];
    const float* beta           = (const float*)d_in[10];
    float* out = (float*)d_out;
    (void)in_sizes; (void)n_in; (void)out_size;

    // Not a stream operation -> capture-safe; idempotent.
    cudaFuncSetAttribute(k_attn, cudaFuncAttributeMaxDynamicSharedMemorySize,
                         ATT_SMEM_BYTES);

    k_mask<<<1, 256>>>(mask_raw);
    k_pair<<<2048, 256>>>(pair, pb_w, pb_b);
    k_qkv<<<dim3(12, 256), 256>>>(msa, qkv_w, qkv_b);
    k_attn<<<dim3(8, 128), 256, ATT_SMEM_BYTES>>>();
    k_proj<<<1024, 256>>>(out_w, out_b, msa);
    k_ln<<<32768, 256>>>(gamma, beta, out);
}

// round 7
// speedup vs baseline: 1.6606x; 1.6606x over previous
#include <cuda_runtime.h>
#include <cstdint>

#define S_DIM 128
#define N_DIM 256
#define C_DIM 256
#define H_DIM 8
#define R_TOT (S_DIM * N_DIM)     // 32768 rows
#define QKV_K 768
#define SCALE_F 0.17677669529663687f
#define NEG_F  (-1000000000.0f)
#define EPS_F  1e-5f

// Scratch (allocation-free rule: __device__ globals)
__device__ float g_qkv[(size_t)R_TOT * QKV_K];          // 96 MB: fused q|k|v rows
__device__ float g_bias[(size_t)H_DIM * N_DIM * N_DIM]; // 2 MB: pair bias [h][n][m]
__device__ float g_att[(size_t)R_TOT * C_DIM];          // 32 MB: attention output
__device__ float g_maskf[S_DIM * N_DIM];                // canonical 0/1 mask

// ---------------------------------------------------------------------------
// tf32 helpers
// ---------------------------------------------------------------------------
__device__ __forceinline__ uint32_t f2tf32(float x) {
    uint32_t r; asm("cvt.rna.tf32.f32 %0, %1;" : "=r"(r) : "f"(x)); return r;
}
__device__ __forceinline__ float f2tf32f(float x) {
    return __uint_as_float(f2tf32(x));
}

#define MMA_TF32(c, a0, a1, a2, a3, b0, b1)                               \
    asm volatile("mma.sync.aligned.m16n8k8.row.col.f32.tf32.tf32.f32 "    \
                 "{%0,%1,%2,%3}, {%4,%5,%6,%7}, {%8,%9}, {%0,%1,%2,%3};"  \
                 : "+f"(c[0]), "+f"(c[1]), "+f"(c[2]), "+f"(c[3])         \
                 : "r"(a0), "r"(a1), "r"(a2), "r"(a3), "r"(b0), "r"(b1))

// ---------------------------------------------------------------------------
// Kernel 0: mask canonicalization (detect uint8/int32/float32 bool storage).
// ---------------------------------------------------------------------------
__global__ void k_mask(const void* __restrict__ mraw) {
    __shared__ int cnt[3];
    const unsigned char* b = (const unsigned char*)mraw;
    const int tid = threadIdx.x;
    if (tid < 3) cnt[tid] = 0;
    __syncthreads();
    int l0 = 0, l1 = 0, l23 = 0;
    for (int i = tid * 16; i < tid * 16 + 16; i++) {
        int nz = (b[i] != 0);
        int p = i & 3;
        if (p == 0) l0 += nz;
        else if (p == 1) l1 += nz;
        else l23 += nz;
    }
    atomicAdd(&cnt[0], l0);
    atomicAdd(&cnt[1], l1);
    atomicAdd(&cnt[2], l23);
    __syncthreads();
    int mode;
    if (cnt[1] > 0) mode = 0;             // uint8 bool
    else if (cnt[0] > 0) mode = 1;        // int32
    else mode = 2;                        // float32
    for (int i = tid; i < S_DIM * N_DIM; i += 256) {
        float v;
        if (mode == 0)      v = (float)b[i];
        else if (mode == 1) v = (float)((const int*)mraw)[i];
        else                v = ((const float*)mraw)[i];
        g_maskf[i] = (v != 0.0f) ? 1.0f : 0.0f;
    }
}

// ---------------------------------------------------------------------------
// Kernel 1: qkv = msa @ qkv_w^T + qkv_b via tf32 mma.sync.
// CTA tile 128(M)x64(N), 8 warps (2M x 4N), warp tile 64x16, K-chunk 32.
// ---------------------------------------------------------------------------
__global__ void __launch_bounds__(256) k_qkv(const float* __restrict__ A,
                                             const float* __restrict__ W,
                                             const float* __restrict__ bias) {
    __shared__ float sm[8704];            // max(As+Bs = 6912, Cs = 8704)
    float* As = sm;                       // [128][36] tf32
    float* Bs = sm + 128 * 36;            // [64][36]  tf32
    float* Cs = sm;                       // epilogue  [128][68]
    const int tid = threadIdx.x, lane = tid & 31, warp = tid >> 5;
    const int lr = lane >> 2, lc = lane & 3;
    const int bm = blockIdx.y * 128, bn = blockIdx.x * 64;
    const int warpM = warp & 1, warpN = warp >> 1;

    float cc[4][2][4];
#pragma unroll
    for (int rt = 0; rt < 4; rt++)
#pragma unroll
        for (int ct = 0; ct < 2; ct++)
#pragma unroll
            for (int i = 0; i < 4; i++) cc[rt][ct][i] = 0.f;

    const uint32_t* Asu = (const uint32_t*)As;
    const uint32_t* Bsu = (const uint32_t*)Bs;

    for (int kt0 = 0; kt0 < 256; kt0 += 32) {
#pragma unroll
        for (int j = 0; j < 4; j++) {     // A: 128x32 = 1024 float4
            int idx = tid + j * 256;
            int row = idx >> 3, kc = (idx & 7) << 2;
            float4 v = *(const float4*)(A + (size_t)(bm + row) * 256 + kt0 + kc);
            float4 t = {f2tf32f(v.x), f2tf32f(v.y), f2tf32f(v.z), f2tf32f(v.w)};
            *(float4*)(As + row * 36 + kc) = t;
        }
#pragma unroll
        for (int j = 0; j < 2; j++) {     // W: 64x32 = 512 float4
            int idx = tid + j * 256;
            int row = idx >> 3, kc = (idx & 7) << 2;
            float4 v = *(const float4*)(W + (size_t)(bn + row) * 256 + kt0 + kc);
            float4 t = {f2tf32f(v.x), f2tf32f(v.y), f2tf32f(v.z), f2tf32f(v.w)};
            *(float4*)(Bs + row * 36 + kc) = t;
        }
        __syncthreads();

#pragma unroll
        for (int kk = 0; kk < 4; kk++) {
            int k0 = kk * 8;
            uint32_t a[4][4];
#pragma unroll
            for (int rt = 0; rt < 4; rt++) {
                int r = warpM * 64 + rt * 16 + lr;
                a[rt][0] = Asu[r * 36 + k0 + lc];
                a[rt][1] = Asu[(r + 8) * 36 + k0 + lc];
                a[rt][2] = Asu[r * 36 + k0 + lc + 4];
                a[rt][3] = Asu[(r + 8) * 36 + k0 + lc + 4];
            }
            uint32_t b[2][2];
#pragma unroll
            for (int ct = 0; ct < 2; ct++) {
                int n = warpN * 16 + ct * 8 + lr;
                b[ct][0] = Bsu[n * 36 + k0 + lc];
                b[ct][1] = Bsu[n * 36 + k0 + lc + 4];
            }
#pragma unroll
            for (int rt = 0; rt < 4; rt++)
#pragma unroll
                for (int ct = 0; ct < 2; ct++)
                    MMA_TF32(cc[rt][ct], a[rt][0], a[rt][1], a[rt][2], a[rt][3],
                             b[ct][0], b[ct][1]);
        }
        __syncthreads();
    }

    // epilogue: frags -> Cs -> coalesced global store with bias
#pragma unroll
    for (int rt = 0; rt < 4; rt++)
#pragma unroll
        for (int ct = 0; ct < 2; ct++) {
            int r = warpM * 64 + rt * 16 + lr;
            int c = warpN * 16 + ct * 8 + 2 * lc;
            Cs[r * 68 + c]           = cc[rt][ct][0];
            Cs[r * 68 + c + 1]       = cc[rt][ct][1];
            Cs[(r + 8) * 68 + c]     = cc[rt][ct][2];
            Cs[(r + 8) * 68 + c + 1] = cc[rt][ct][3];
        }
    __syncthreads();
#pragma unroll
    for (int j = 0; j < 8; j++) {        // 128x64 = 2048 float4
        int idx = tid + j * 256;
        int row = idx >> 4, c4 = (idx & 15) << 2;
        float4 v  = *(const float4*)(Cs + row * 68 + c4);
        float4 bb = *(const float4*)(bias + bn + c4);
        v.x += bb.x; v.y += bb.y; v.z += bb.z; v.w += bb.w;
        *(float4*)(g_qkv + (size_t)(bm + row) * QKV_K + bn + c4) = v;
    }
}

// ---------------------------------------------------------------------------
// Kernel 2: pair bias.  bias[h][n][m] = dot(pair[n][m][:], pb_w[h][:]) + pb_b[h]
// ---------------------------------------------------------------------------
__global__ void __launch_bounds__(256) k_pair(const float* __restrict__ pair,
                                              const float* __restrict__ pw,
                                              const float* __restrict__ pb) {
    __shared__ float pr[32][128];
    __shared__ float ws[8 * 128];
    const int tid = threadIdx.x;
    const int rb = blockIdx.x * 32;

    ((float4*)ws)[tid] = ((const float4*)pw)[tid];
#pragma unroll
    for (int j = 0; j < 4; j++) {
        int chunk = tid + j * 256;
        int r = chunk >> 5, pc = (chunk & 31) << 2;
        *(float4*)&pr[r][pc] = *(const float4*)(pair + (size_t)(rb + r) * 128 + pc);
    }
    __syncthreads();

    const int r = tid >> 3, h = tid & 7;
    const float* wr = ws + h * 128;
    float s = 0.f;
#pragma unroll
    for (int p = 0; p < 128; p += 4) {
        float4 a = *(const float4*)&pr[r][p];
        float4 w = *(const float4*)(wr + p);
        s += a.x * w.x + a.y * w.y + a.z * w.z + a.w * w.w;
    }
    g_bias[(size_t)h * (N_DIM * N_DIM) + rb + r] = s + pb[h];
}

// ---------------------------------------------------------------------------
// Kernel 3: attention via tf32 mma. One CTA per (s,h).
// K in smem [m][d] (stride 36 = natural col-major B for QK^T).
// V^T in smem [d][m] (stride 264 = col-major B for PV).
// Scores [n][m] (stride 264 = row-major A for PV; row-wise coalesced softmax).
// ---------------------------------------------------------------------------
#define AT_SMEM_FLOATS (9216 + 8448 + 8448 + 1152 + 256 + 32)
#define AT_SMEM_BYTES  (AT_SMEM_FLOATS * 4)

__global__ void __launch_bounds__(256) k_attn() {
    extern __shared__ float smf[];
    float* ks   = smf;            // [256][36]  K, tf32
    float* vt   = ks + 9216;      // [32][264]  V^T, tf32
    float* sc2  = vt + 8448;      // [32][264]  scores / exp (exp stored tf32)
    float* qs   = sc2 + 8448;     // [32][36]   Q chunk, tf32
    float* mk   = qs + 1152;      // [256]
    float* invs = mk + 256;       // [32]

    const int h = blockIdx.x, s = blockIdx.y;
    const int tid = threadIdx.x, lane = tid & 31, warp = tid >> 5;
    const int lr = lane >> 2, lc = lane & 3;

    mk[tid] = g_maskf[s * 256 + tid];
    {   // stage K [m][d] and V^T [d][m]; m = tid
        const float* kb = g_qkv + (size_t)(s * 256 + tid) * QKV_K + 256 + h * 32;
        const float* vb = kb + 256;
#pragma unroll
        for (int d4 = 0; d4 < 8; d4++) {
            float4 kv = *(const float4*)(kb + d4 * 4);
            float4 vv = *(const float4*)(vb + d4 * 4);
            float4 kt4 = {f2tf32f(kv.x), f2tf32f(kv.y), f2tf32f(kv.z), f2tf32f(kv.w)};
            *(float4*)(ks + tid * 36 + d4 * 4) = kt4;
            vt[(d4 * 4 + 0) * 264 + tid] = f2tf32f(vv.x);
            vt[(d4 * 4 + 1) * 264 + tid] = f2tf32f(vv.y);
            vt[(d4 * 4 + 2) * 264 + tid] = f2tf32f(vv.z);
            vt[(d4 * 4 + 3) * 264 + tid] = f2tf32f(vv.w);
        }
    }
    __syncthreads();

    const uint32_t* ksu = (const uint32_t*)ks;
    const uint32_t* qsu = (const uint32_t*)qs;
    const uint32_t* su  = (const uint32_t*)sc2;
    const uint32_t* vu  = (const uint32_t*)vt;

    for (int qc = 0; qc < 8; qc++) {
        const int n0g = qc * 32;
        {   // stage Q chunk [n][d]
            int n = tid >> 3, dc = (tid & 7) << 2;
            float4 v = *(const float4*)(g_qkv + (size_t)(s * 256 + n0g + n) * QKV_K + h * 32 + dc);
            float4 t = {f2tf32f(v.x), f2tf32f(v.y), f2tf32f(v.z), f2tf32f(v.w)};
            *(float4*)(qs + n * 36 + dc) = t;
        }
        __syncthreads();

        // --- QK^T: warp owns m-strip [warp*32, warp*32+32) over all 32 queries
        float cc[2][4][4];
#pragma unroll
        for (int rt = 0; rt < 2; rt++)
#pragma unroll
            for (int ct = 0; ct < 4; ct++)
#pragma unroll
                for (int i = 0; i < 4; i++) cc[rt][ct][i] = 0.f;

#pragma unroll
        for (int kt = 0; kt < 4; kt++) {
            int k0 = kt * 8;
            uint32_t a[2][4];
#pragma unroll
            for (int rt = 0; rt < 2; rt++) {
                int r = rt * 16 + lr;
                a[rt][0] = qsu[r * 36 + k0 + lc];
                a[rt][1] = qsu[(r + 8) * 36 + k0 + lc];
                a[rt][2] = qsu[r * 36 + k0 + lc + 4];
                a[rt][3] = qsu[(r + 8) * 36 + k0 + lc + 4];
            }
#pragma unroll
            for (int ct = 0; ct < 4; ct++) {
                int m0 = warp * 32 + ct * 8;
                uint32_t b0 = ksu[(m0 + lr) * 36 + k0 + lc];
                uint32_t b1 = ksu[(m0 + lr) * 36 + k0 + lc + 4];
                MMA_TF32(cc[0][ct], a[0][0], a[0][1], a[0][2], a[0][3], b0, b1);
                MMA_TF32(cc[1][ct], a[1][0], a[1][1], a[1][2], a[1][3], b0, b1);
            }
        }
        // store raw scores to sc2[n][m]
#pragma unroll
        for (int rt = 0; rt < 2; rt++)
#pragma unroll
            for (int ct = 0; ct < 4; ct++) {
                int r = rt * 16 + lr, c = warp * 32 + ct * 8 + 2 * lc;
                sc2[r * 264 + c]           = cc[rt][ct][0];
                sc2[r * 264 + c + 1]       = cc[rt][ct][1];
                sc2[(r + 8) * 264 + c]     = cc[rt][ct][2];
                sc2[(r + 8) * 264 + c + 1] = cc[rt][ct][3];
            }
        __syncthreads();

        // --- softmax: warp handles rows n = warp*4 .. warp*4+3, coalesced in m
#pragma unroll
        for (int rr = 0; rr < 4; rr++) {
            int n = warp * 4 + rr, gn = n0g + n;
            float mn = mk[gn];
            const float* brow = g_bias + ((size_t)h * 256 + gn) * 256;
            float x[8], mx = -3.4e38f;
#pragma unroll
            for (int j = 0; j < 8; j++) {
                int m = lane + j * 32;
                float v = sc2[n * 264 + m] * SCALE_F;
                if (mn * mk[m] < 0.5f) v = NEG_F;
                v += brow[m];
                x[j] = v;
                mx = fmaxf(mx, v);
            }
#pragma unroll
            for (int off = 16; off > 0; off >>= 1)
                mx = fmaxf(mx, __shfl_xor_sync(0xffffffffu, mx, off));
            float sum = 0.f;
#pragma unroll
            for (int j = 0; j < 8; j++) {
                float e = __expf(x[j] - mx);
                sum += e;
                sc2[n * 264 + lane + j * 32] = f2tf32f(e);
            }
#pragma unroll
            for (int off = 16; off > 0; off >>= 1)
                sum += __shfl_xor_sync(0xffffffffu, sum, off);
            if (lane == 0) invs[n] = 1.0f / sum;
        }
        __syncthreads();

        // --- PV: warp -> output tile (rt = warp&1 [16 rows n], ct = warp>>1 [8 cols d])
        {
            int rt = warp & 1, ct = warp >> 1;
            float o[4] = {0.f, 0.f, 0.f, 0.f};
#pragma unroll
            for (int km = 0; km < 32; km++) {
                int m0 = km * 8;
                uint32_t a0 = su[(rt * 16 + lr) * 264 + m0 + lc];
                uint32_t a1 = su[(rt * 16 + lr + 8) * 264 + m0 + lc];
                uint32_t a2 = su[(rt * 16 + lr) * 264 + m0 + lc + 4];
                uint32_t a3 = su[(rt * 16 + lr + 8) * 264 + m0 + lc + 4];
                uint32_t b0 = vu[(ct * 8 + lr) * 264 + m0 + lc];
                uint32_t b1 = vu[(ct * 8 + lr) * 264 + m0 + lc + 4];
                MMA_TF32(o, a0, a1, a2, a3, b0, b1);
            }
            int r = rt * 16 + lr, d0 = ct * 8 + 2 * lc;
            float i0 = invs[r], i1 = invs[r + 8];
            *(float2*)(g_att + (size_t)(s * 256 + n0g + r) * 256 + h * 32 + d0) =
                make_float2(o[0] * i0, o[1] * i0);
            *(float2*)(g_att + (size_t)(s * 256 + n0g + r + 8) * 256 + h * 32 + d0) =
                make_float2(o[2] * i1, o[3] * i1);
        }
        __syncthreads();
    }
}

// ---------------------------------------------------------------------------
// Kernel 4: out-proj + bias + residual + LayerNorm, fused.
// out = LN(msa + g_att @ out_w^T + out_b).
// Tile 32 rows x 256 cols. Each warp owns 4 full rows (lane = 8-col chunk),
// so LN mean/var are warp-shuffle reductions; writes final output directly.
// ---------------------------------------------------------------------------
__global__ void __launch_bounds__(256) k_proj(const float* __restrict__ W,
                                              const float* __restrict__ bias,
                                              const float* __restrict__ msa,
                                              const float* __restrict__ gamma,
                                              const float* __restrict__ beta,
                                              float* __restrict__ out) {
    __shared__ float As[256 * 32];   // As[k*32 + r]
    __shared__ float Ws[16][264];
    const int tid = threadIdx.x;
    const int bm = blockIdx.x * 32;

    {   // stage full A tile transposed (32 x 256)
        int r = tid >> 3, c0 = (tid & 7) << 5;
        const float* ar = g_att + (size_t)(bm + r) * 256 + c0;
#pragma unroll
        for (int j = 0; j < 8; j++) {
            float4 v = *(const float4*)(ar + j * 4);
            As[(c0 + j * 4 + 0) * 32 + r] = v.x;
            As[(c0 + j * 4 + 1) * 32 + r] = v.y;
            As[(c0 + j * 4 + 2) * 32 + r] = v.z;
            As[(c0 + j * 4 + 3) * 32 + r] = v.w;
        }
    }
    const int txc = tid & 31, tyr = tid >> 5;
    const int c0 = txc * 8, r0 = tyr * 4;

    float acc[4][8];
#pragma unroll
    for (int i = 0; i < 4; i++)
#pragma unroll
        for (int j = 0; j < 8; j++) acc[i][j] = 0.f;

    for (int kt = 0; kt < 256; kt += 16) {
        __syncthreads();   // covers first-iter A staging + Ws reuse
#pragma unroll
        for (int j = 0; j < 4; j++) {    // W tile 256x16 = 1024 float4s
            int chunk = tid + j * 256;
            int c = chunk >> 2, kc = (chunk & 3) << 2;
            float4 v = *(const float4*)(W + (size_t)c * 256 + kt + kc);
            Ws[kc + 0][c] = v.x; Ws[kc + 1][c] = v.y;
            Ws[kc + 2][c] = v.z; Ws[kc + 3][c] = v.w;
        }
        __syncthreads();
#pragma unroll
        for (int k = 0; k < 16; k++) {
            float4 a  = *(const float4*)(As + (kt + k) * 32 + r0);
            float4 w0 = *(const float4*)&Ws[k][c0];
            float4 w1 = *(const float4*)&Ws[k][c0 + 4];
            float av[4] = {a.x, a.y, a.z, a.w};
            float wv[8] = {w0.x, w0.y, w0.z, w0.w, w1.x, w1.y, w1.z, w1.w};
#pragma unroll
            for (int i = 0; i < 4; i++)
#pragma unroll
                for (int j = 0; j < 8; j++) acc[i][j] += av[i] * wv[j];
        }
    }

    float4 bb0 = *(const float4*)(bias + c0);
    float4 bb1 = *(const float4*)(bias + c0 + 4);
    float4 gg0 = *(const float4*)(gamma + c0);
    float4 gg1 = *(const float4*)(gamma + c0 + 4);
    float4 be0 = *(const float4*)(beta + c0);
    float4 be1 = *(const float4*)(beta + c0 + 4);
    const float bbv[8] = {bb0.x, bb0.y, bb0.z, bb0.w, bb1.x, bb1.y, bb1.z, bb1.w};
    const float ggv[8] = {gg0.x, gg0.y, gg0.z, gg0.w, gg1.x, gg1.y, gg1.z, gg1.w};
    const float bev[8] = {be0.x, be0.y, be0.z, be0.w, be1.x, be1.y, be1.z, be1.w};

#pragma unroll
    for (int i = 0; i < 4; i++) {
        int r = bm + r0 + i;
        const float* mrow = msa + (size_t)r * 256;
        float4 m0 = *(const float4*)(mrow + c0);
        float4 m1 = *(const float4*)(mrow + c0 + 4);
        const float mv[8] = {m0.x, m0.y, m0.z, m0.w, m1.x, m1.y, m1.z, m1.w};
        float v[8], s = 0.f;
#pragma unroll
        for (int j = 0; j < 8; j++) {
            v[j] = acc[i][j] + bbv[j] + mv[j];
            s += v[j];
        }
#pragma unroll
        for (int off = 16; off > 0; off >>= 1)
            s += __shfl_xor_sync(0xffffffffu, s, off);
        float mu = s * (1.0f / 256.0f);
        float s2 = 0.f;
#pragma unroll
        for (int j = 0; j < 8; j++) {
            v[j] -= mu;
            s2 += v[j] * v[j];
        }
#pragma unroll
        for (int off = 16; off > 0; off >>= 1)
            s2 += __shfl_xor_sync(0xffffffffu, s2, off);
        float rs = rsqrtf(s2 * (1.0f / 256.0f) + EPS_F);
        float4 o0, o1;
        o0.x = v[0] * rs * ggv[0] + bev[0];
        o0.y = v[1] * rs * ggv[1] + bev[1];
        o0.z = v[2] * rs * ggv[2] + bev[2];
        o0.w = v[3] * rs * ggv[3] + bev[3];
        o1.x = v[4] * rs * ggv[4] + bev[4];
        o1.y = v[5] * rs * ggv[5] + bev[5];
        o1.z = v[6] * rs * ggv[6] + bev[6];
        o1.w = v[7] * rs * ggv[7] + bev[7];
        *(float4*)(out + (size_t)r * 256 + c0)     = o0;
        *(float4*)(out + (size_t)r * 256 + c0 + 4) = o1;
    }
}

// ---------------------------------------------------------------------------
extern "C" void kernel_launch(void* const* d_in, const int* in_sizes, int n_in,
                              void* d_out, int out_size) {
    const float* msa            = (const float*)d_in[0];
    const float* pair           = (const float*)d_in[1];
    const void*  mask_raw       = (const void*)d_in[2];
    const float* qkv_w          = (const float*)d_in[3];
    const float* qkv_b          = (const float*)d_in[4];
    const float* out_w          = (const float*)d_in[5];
    const float* out_b          = (const float*)d_in[6];
    const float* pb_w           = (const float*)d_in[7];
    const float* pb_b           = (const float*)d_in[8];
    const float* gamma          = (const float*)d_in[9];
    const float* beta           = (const float*)d_in[10];
    float* out = (float*)d_out;
    (void)in_sizes; (void)n_in; (void)out_size;

    cudaFuncSetAttribute(k_attn, cudaFuncAttributeMaxDynamicSharedMemorySize,
                         AT_SMEM_BYTES);

    k_mask<<<1, 256>>>(mask_raw);
    k_pair<<<2048, 256>>>(pair, pb_w, pb_b);
    k_qkv<<<dim3(12, 256), 256>>>(msa, qkv_w, qkv_b);
    k_attn<<<dim3(8, 128), 256, AT_SMEM_BYTES>>>();
    k_proj<<<1024, 256>>>(out_w, out_b, msa, gamma, beta, out);
}

// round 8
// speedup vs baseline: 2.0966x; 1.2625x over previous
#include <cuda_runtime.h>
#include <cstdint>

#define S_DIM 128
#define N_DIM 256
#define C_DIM 256
#define H_DIM 8
#define R_TOT (S_DIM * N_DIM)     // 32768 rows
#define QKV_K 768
#define SCALE_F 0.17677669529663687f
#define NEG_F  (-1000000000.0f)
#define EPS_F  1e-5f

// Scratch (allocation-free rule: __device__ globals)
__device__ float g_qkv[(size_t)R_TOT * QKV_K];          // 96 MB: fused q|k|v rows
__device__ float g_bias[(size_t)H_DIM * N_DIM * N_DIM]; // 2 MB: pair bias [h][n][m]
__device__ float g_att[(size_t)R_TOT * C_DIM];          // 32 MB: attention output
__device__ float g_maskf[S_DIM * N_DIM];                // canonical 0/1 mask

// ---------------------------------------------------------------------------
// tf32 helpers
// ---------------------------------------------------------------------------
__device__ __forceinline__ uint32_t f2tf32(float x) {
    uint32_t r; asm("cvt.rna.tf32.f32 %0, %1;" : "=r"(r) : "f"(x)); return r;
}
__device__ __forceinline__ float f2tf32f(float x) {
    return __uint_as_float(f2tf32(x));
}

#define MMA_TF32(c, a0, a1, a2, a3, b0, b1)                               \
    asm volatile("mma.sync.aligned.m16n8k8.row.col.f32.tf32.tf32.f32 "    \
                 "{%0,%1,%2,%3}, {%4,%5,%6,%7}, {%8,%9}, {%0,%1,%2,%3};"  \
                 : "+f"(c[0]), "+f"(c[1]), "+f"(c[2]), "+f"(c[3])         \
                 : "r"(a0), "r"(a1), "r"(a2), "r"(a3), "r"(b0), "r"(b1))

// ---------------------------------------------------------------------------
// Kernel 0: mask canonicalization (detect uint8/int32/float32 bool storage).
// ---------------------------------------------------------------------------
__global__ void k_mask(const void* __restrict__ mraw) {
    __shared__ int cnt[3];
    const unsigned char* b = (const unsigned char*)mraw;
    const int tid = threadIdx.x;
    if (tid < 3) cnt[tid] = 0;
    __syncthreads();
    int l0 = 0, l1 = 0, l23 = 0;
    for (int i = tid * 16; i < tid * 16 + 16; i++) {
        int nz = (b[i] != 0);
        int p = i & 3;
        if (p == 0) l0 += nz;
        else if (p == 1) l1 += nz;
        else l23 += nz;
    }
    atomicAdd(&cnt[0], l0);
    atomicAdd(&cnt[1], l1);
    atomicAdd(&cnt[2], l23);
    __syncthreads();
    int mode;
    if (cnt[1] > 0) mode = 0;             // uint8 bool
    else if (cnt[0] > 0) mode = 1;        // int32
    else mode = 2;                        // float32
    for (int i = tid; i < S_DIM * N_DIM; i += 256) {
        float v;
        if (mode == 0)      v = (float)b[i];
        else if (mode == 1) v = (float)((const int*)mraw)[i];
        else                v = ((const float*)mraw)[i];
        g_maskf[i] = (v != 0.0f) ? 1.0f : 0.0f;
    }
}

// ---------------------------------------------------------------------------
// Kernel 1: qkv = msa @ qkv_w^T + qkv_b via tf32 mma.sync.
// CTA tile 128(M)x64(N), 8 warps (2M x 4N), warp tile 64x16, K-chunk 32.
// ---------------------------------------------------------------------------
__global__ void __launch_bounds__(256) k_qkv(const float* __restrict__ A,
                                             const float* __restrict__ W,
                                             const float* __restrict__ bias) {
    __shared__ float sm[8704];            // max(As+Bs = 6912, Cs = 8704)
    float* As = sm;                       // [128][36] tf32
    float* Bs = sm + 128 * 36;            // [64][36]  tf32
    float* Cs = sm;                       // epilogue  [128][68]
    const int tid = threadIdx.x, lane = tid & 31, warp = tid >> 5;
    const int lr = lane >> 2, lc = lane & 3;
    const int bm = blockIdx.y * 128, bn = blockIdx.x * 64;
    const int warpM = warp & 1, warpN = warp >> 1;

    float cc[4][2][4];
#pragma unroll
    for (int rt = 0; rt < 4; rt++)
#pragma unroll
        for (int ct = 0; ct < 2; ct++)
#pragma unroll
            for (int i = 0; i < 4; i++) cc[rt][ct][i] = 0.f;

    const uint32_t* Asu = (const uint32_t*)As;
    const uint32_t* Bsu = (const uint32_t*)Bs;

    for (int kt0 = 0; kt0 < 256; kt0 += 32) {
#pragma unroll
        for (int j = 0; j < 4; j++) {     // A: 128x32 = 1024 float4
            int idx = tid + j * 256;
            int row = idx >> 3, kc = (idx & 7) << 2;
            float4 v = *(const float4*)(A + (size_t)(bm + row) * 256 + kt0 + kc);
            float4 t = {f2tf32f(v.x), f2tf32f(v.y), f2tf32f(v.z), f2tf32f(v.w)};
            *(float4*)(As + row * 36 + kc) = t;
        }
#pragma unroll
        for (int j = 0; j < 2; j++) {     // W: 64x32 = 512 float4
            int idx = tid + j * 256;
            int row = idx >> 3, kc = (idx & 7) << 2;
            float4 v = *(const float4*)(W + (size_t)(bn + row) * 256 + kt0 + kc);
            float4 t = {f2tf32f(v.x), f2tf32f(v.y), f2tf32f(v.z), f2tf32f(v.w)};
            *(float4*)(Bs + row * 36 + kc) = t;
        }
        __syncthreads();

#pragma unroll
        for (int kk = 0; kk < 4; kk++) {
            int k0 = kk * 8;
            uint32_t a[4][4];
#pragma unroll
            for (int rt = 0; rt < 4; rt++) {
                int r = warpM * 64 + rt * 16 + lr;
                a[rt][0] = Asu[r * 36 + k0 + lc];
                a[rt][1] = Asu[(r + 8) * 36 + k0 + lc];
                a[rt][2] = Asu[r * 36 + k0 + lc + 4];
                a[rt][3] = Asu[(r + 8) * 36 + k0 + lc + 4];
            }
            uint32_t b[2][2];
#pragma unroll
            for (int ct = 0; ct < 2; ct++) {
                int n = warpN * 16 + ct * 8 + lr;
                b[ct][0] = Bsu[n * 36 + k0 + lc];
                b[ct][1] = Bsu[n * 36 + k0 + lc + 4];
            }
#pragma unroll
            for (int rt = 0; rt < 4; rt++)
#pragma unroll
                for (int ct = 0; ct < 2; ct++)
                    MMA_TF32(cc[rt][ct], a[rt][0], a[rt][1], a[rt][2], a[rt][3],
                             b[ct][0], b[ct][1]);
        }
        __syncthreads();
    }

    // epilogue: frags -> Cs -> coalesced global store with bias
#pragma unroll
    for (int rt = 0; rt < 4; rt++)
#pragma unroll
        for (int ct = 0; ct < 2; ct++) {
            int r = warpM * 64 + rt * 16 + lr;
            int c = warpN * 16 + ct * 8 + 2 * lc;
            Cs[r * 68 + c]           = cc[rt][ct][0];
            Cs[r * 68 + c + 1]       = cc[rt][ct][1];
            Cs[(r + 8) * 68 + c]     = cc[rt][ct][2];
            Cs[(r + 8) * 68 + c + 1] = cc[rt][ct][3];
        }
    __syncthreads();
#pragma unroll
    for (int j = 0; j < 8; j++) {        // 128x64 = 2048 float4
        int idx = tid + j * 256;
        int row = idx >> 4, c4 = (idx & 15) << 2;
        float4 v  = *(const float4*)(Cs + row * 68 + c4);
        float4 bb = *(const float4*)(bias + bn + c4);
        v.x += bb.x; v.y += bb.y; v.z += bb.z; v.w += bb.w;
        *(float4*)(g_qkv + (size_t)(bm + row) * QKV_K + bn + c4) = v;
    }
}

// ---------------------------------------------------------------------------
// Kernel 2: pair bias.  bias[h][n][m] = dot(pair[n][m][:], pb_w[h][:]) + pb_b[h]
// ---------------------------------------------------------------------------
__global__ void __launch_bounds__(256) k_pair(const float* __restrict__ pair,
                                              const float* __restrict__ pw,
                                              const float* __restrict__ pb) {
    __shared__ float pr[32][128];
    __shared__ float ws[8 * 128];
    const int tid = threadIdx.x;
    const int rb = blockIdx.x * 32;

    ((float4*)ws)[tid] = ((const float4*)pw)[tid];
#pragma unroll
    for (int j = 0; j < 4; j++) {
        int chunk = tid + j * 256;
        int r = chunk >> 5, pc = (chunk & 31) << 2;
        *(float4*)&pr[r][pc] = *(const float4*)(pair + (size_t)(rb + r) * 128 + pc);
    }
    __syncthreads();

    const int r = tid >> 3, h = tid & 7;
    const float* wr = ws + h * 128;
    float s = 0.f;
#pragma unroll
    for (int p = 0; p < 128; p += 4) {
        float4 a = *(const float4*)&pr[r][p];
        float4 w = *(const float4*)(wr + p);
        s += a.x * w.x + a.y * w.y + a.z * w.z + a.w * w.w;
    }
    g_bias[(size_t)h * (N_DIM * N_DIM) + rb + r] = s + pb[h];
}

// ---------------------------------------------------------------------------
// Kernel 3: attention via tf32 mma. One CTA per (s,h).
// (unchanged from Round 7 — 248us, next target after k_proj)
// ---------------------------------------------------------------------------
#define AT_SMEM_FLOATS (9216 + 8448 + 8448 + 1152 + 256 + 32)
#define AT_SMEM_BYTES  (AT_SMEM_FLOATS * 4)

__global__ void __launch_bounds__(256) k_attn() {
    extern __shared__ float smf[];
    float* ks   = smf;            // [256][36]  K, tf32
    float* vt   = ks + 9216;      // [32][264]  V^T, tf32
    float* sc2  = vt + 8448;      // [32][264]  scores / exp (exp stored tf32)
    float* qs   = sc2 + 8448;     // [32][36]   Q chunk, tf32
    float* mk   = qs + 1152;      // [256]
    float* invs = mk + 256;       // [32]

    const int h = blockIdx.x, s = blockIdx.y;
    const int tid = threadIdx.x, lane = tid & 31, warp = tid >> 5;
    const int lr = lane >> 2, lc = lane & 3;

    mk[tid] = g_maskf[s * 256 + tid];
    {   // stage K [m][d] and V^T [d][m]; m = tid
        const float* kb = g_qkv + (size_t)(s * 256 + tid) * QKV_K + 256 + h * 32;
        const float* vb = kb + 256;
#pragma unroll
        for (int d4 = 0; d4 < 8; d4++) {
            float4 kv = *(const float4*)(kb + d4 * 4);
            float4 vv = *(const float4*)(vb + d4 * 4);
            float4 kt4 = {f2tf32f(kv.x), f2tf32f(kv.y), f2tf32f(kv.z), f2tf32f(kv.w)};
            *(float4*)(ks + tid * 36 + d4 * 4) = kt4;
            vt[(d4 * 4 + 0) * 264 + tid] = f2tf32f(vv.x);
            vt[(d4 * 4 + 1) * 264 + tid] = f2tf32f(vv.y);
            vt[(d4 * 4 + 2) * 264 + tid] = f2tf32f(vv.z);
            vt[(d4 * 4 + 3) * 264 + tid] = f2tf32f(vv.w);
        }
    }
    __syncthreads();

    const uint32_t* ksu = (const uint32_t*)ks;
    const uint32_t* qsu = (const uint32_t*)qs;
    const uint32_t* su  = (const uint32_t*)sc2;
    const uint32_t* vu  = (const uint32_t*)vt;

    for (int qc = 0; qc < 8; qc++) {
        const int n0g = qc * 32;
        {   // stage Q chunk [n][d]
            int n = tid >> 3, dc = (tid & 7) << 2;
            float4 v = *(const float4*)(g_qkv + (size_t)(s * 256 + n0g + n) * QKV_K + h * 32 + dc);
            float4 t = {f2tf32f(v.x), f2tf32f(v.y), f2tf32f(v.z), f2tf32f(v.w)};
            *(float4*)(qs + n * 36 + dc) = t;
        }
        __syncthreads();

        // --- QK^T: warp owns m-strip [warp*32, warp*32+32) over all 32 queries
        float cc[2][4][4];
#pragma unroll
        for (int rt = 0; rt < 2; rt++)
#pragma unroll
            for (int ct = 0; ct < 4; ct++)
#pragma unroll
                for (int i = 0; i < 4; i++) cc[rt][ct][i] = 0.f;

#pragma unroll
        for (int kt = 0; kt < 4; kt++) {
            int k0 = kt * 8;
            uint32_t a[2][4];
#pragma unroll
            for (int rt = 0; rt < 2; rt++) {
                int r = rt * 16 + lr;
                a[rt][0] = qsu[r * 36 + k0 + lc];
                a[rt][1] = qsu[(r + 8) * 36 + k0 + lc];
                a[rt][2] = qsu[r * 36 + k0 + lc + 4];
                a[rt][3] = qsu[(r + 8) * 36 + k0 + lc + 4];
            }
#pragma unroll
            for (int ct = 0; ct < 4; ct++) {
                int m0 = warp * 32 + ct * 8;
                uint32_t b0 = ksu[(m0 + lr) * 36 + k0 + lc];
                uint32_t b1 = ksu[(m0 + lr) * 36 + k0 + lc + 4];
                MMA_TF32(cc[0][ct], a[0][0], a[0][1], a[0][2], a[0][3], b0, b1);
                MMA_TF32(cc[1][ct], a[1][0], a[1][1], a[1][2], a[1][3], b0, b1);
            }
        }
        // store raw scores to sc2[n][m]
#pragma unroll
        for (int rt = 0; rt < 2; rt++)
#pragma unroll
            for (int ct = 0; ct < 4; ct++) {
                int r = rt * 16 + lr, c = warp * 32 + ct * 8 + 2 * lc;
                sc2[r * 264 + c]           = cc[rt][ct][0];
                sc2[r * 264 + c + 1]       = cc[rt][ct][1];
                sc2[(r + 8) * 264 + c]     = cc[rt][ct][2];
                sc2[(r + 8) * 264 + c + 1] = cc[rt][ct][3];
            }
        __syncthreads();

        // --- softmax: warp handles rows n = warp*4 .. warp*4+3, coalesced in m
#pragma unroll
        for (int rr = 0; rr < 4; rr++) {
            int n = warp * 4 + rr, gn = n0g + n;
            float mn = mk[gn];
            const float* brow = g_bias + ((size_t)h * 256 + gn) * 256;
            float x[8], mx = -3.4e38f;
#pragma unroll
            for (int j = 0; j < 8; j++) {
                int m = lane + j * 32;
                float v = sc2[n * 264 + m] * SCALE_F;
                if (mn * mk[m] < 0.5f) v = NEG_F;
                v += brow[m];
                x[j] = v;
                mx = fmaxf(mx, v);
            }
#pragma unroll
            for (int off = 16; off > 0; off >>= 1)
                mx = fmaxf(mx, __shfl_xor_sync(0xffffffffu, mx, off));
            float sum = 0.f;
#pragma unroll
            for (int j = 0; j < 8; j++) {
                float e = __expf(x[j] - mx);
                sum += e;
                sc2[n * 264 + lane + j * 32] = f2tf32f(e);
            }
#pragma unroll
            for (int off = 16; off > 0; off >>= 1)
                sum += __shfl_xor_sync(0xffffffffu, sum, off);
            if (lane == 0) invs[n] = 1.0f / sum;
        }
        __syncthreads();

        // --- PV: warp -> output tile (rt = warp&1 [16 rows n], ct = warp>>1 [8 cols d])
        {
            int rt = warp & 1, ct = warp >> 1;
            float o[4] = {0.f, 0.f, 0.f, 0.f};
#pragma unroll
            for (int km = 0; km < 32; km++) {
                int m0 = km * 8;
                uint32_t a0 = su[(rt * 16 + lr) * 264 + m0 + lc];
                uint32_t a1 = su[(rt * 16 + lr + 8) * 264 + m0 + lc];
                uint32_t a2 = su[(rt * 16 + lr) * 264 + m0 + lc + 4];
                uint32_t a3 = su[(rt * 16 + lr + 8) * 264 + m0 + lc + 4];
                uint32_t b0 = vu[(ct * 8 + lr) * 264 + m0 + lc];
                uint32_t b1 = vu[(ct * 8 + lr) * 264 + m0 + lc + 4];
                MMA_TF32(o, a0, a1, a2, a3, b0, b1);
            }
            int r = rt * 16 + lr, d0 = ct * 8 + 2 * lc;
            float i0 = invs[r], i1 = invs[r + 8];
            *(float2*)(g_att + (size_t)(s * 256 + n0g + r) * 256 + h * 32 + d0) =
                make_float2(o[0] * i0, o[1] * i0);
            *(float2*)(g_att + (size_t)(s * 256 + n0g + r + 8) * 256 + h * 32 + d0) =
                make_float2(o[2] * i1, o[3] * i1);
        }
        __syncthreads();
    }
}

// ---------------------------------------------------------------------------
// Kernel 4: out-proj + bias + residual + LayerNorm, fused, tf32 mma.
// out = LN(msa + g_att @ out_w^T + out_b).
// CTA = 64 rows x 256 cols (full N so LN stays intra-CTA). 8 warps, each owns
// a 32-col strip: 4(rt, 16-row) x 4(ct, 8-col) m16n8k8 tiles, K-chunk 32.
// Epilogue: frags -> Cs[64][264] -> warp-per-8-rows shuffle-LN -> out.
// ---------------------------------------------------------------------------
#define PROJ_SMEM_FLOATS 16896           // max(As 2304 + Bs 9216, Cs 64*264)
#define PROJ_SMEM_BYTES  (PROJ_SMEM_FLOATS * 4)

__global__ void __launch_bounds__(256) k_proj(const float* __restrict__ W,
                                              const float* __restrict__ bias,
                                              const float* __restrict__ msa,
                                              const float* __restrict__ gamma,
                                              const float* __restrict__ beta,
                                              float* __restrict__ out) {
    extern __shared__ float psm[];
    float* As = psm;                 // [64][36]  tf32
    float* Bs = psm + 64 * 36;       // [256][36] tf32
    float* Cs = psm;                 // epilogue [64][264]
    const int tid = threadIdx.x, lane = tid & 31, warp = tid >> 5;
    const int lr = lane >> 2, lc = lane & 3;
    const int bm = blockIdx.x * 64;

    float acc[4][4][4];
#pragma unroll
    for (int rt = 0; rt < 4; rt++)
#pragma unroll
        for (int ct = 0; ct < 4; ct++)
#pragma unroll
            for (int i = 0; i < 4; i++) acc[rt][ct][i] = 0.f;

    const uint32_t* Asu = (const uint32_t*)As;
    const uint32_t* Bsu = (const uint32_t*)Bs;

    for (int kt0 = 0; kt0 < 256; kt0 += 32) {
#pragma unroll
        for (int j = 0; j < 2; j++) {    // A: 64x32 = 512 float4
            int idx = tid + j * 256;
            int row = idx >> 3, kc = (idx & 7) << 2;
            float4 v = *(const float4*)(g_att + (size_t)(bm + row) * 256 + kt0 + kc);
            float4 t = {f2tf32f(v.x), f2tf32f(v.y), f2tf32f(v.z), f2tf32f(v.w)};
            *(float4*)(As + row * 36 + kc) = t;
        }
#pragma unroll
        for (int j = 0; j < 8; j++) {    // W: 256x32 = 2048 float4
            int idx = tid + j * 256;
            int n = idx >> 3, kc = (idx & 7) << 2;
            float4 v = *(const float4*)(W + (size_t)n * 256 + kt0 + kc);
            float4 t = {f2tf32f(v.x), f2tf32f(v.y), f2tf32f(v.z), f2tf32f(v.w)};
            *(float4*)(Bs + n * 36 + kc) = t;
        }
        __syncthreads();

#pragma unroll
        for (int kk = 0; kk < 4; kk++) {
            int k0 = kk * 8;
            uint32_t a[4][4];
#pragma unroll
            for (int rt = 0; rt < 4; rt++) {
                int r = rt * 16 + lr;
                a[rt][0] = Asu[r * 36 + k0 + lc];
                a[rt][1] = Asu[(r + 8) * 36 + k0 + lc];
                a[rt][2] = Asu[r * 36 + k0 + lc + 4];
                a[rt][3] = Asu[(r + 8) * 36 + k0 + lc + 4];
            }
            uint32_t b[4][2];
#pragma unroll
            for (int ct = 0; ct < 4; ct++) {
                int n = warp * 32 + ct * 8 + lr;
                b[ct][0] = Bsu[n * 36 + k0 + lc];
                b[ct][1] = Bsu[n * 36 + k0 + lc + 4];
            }
#pragma unroll
            for (int rt = 0; rt < 4; rt++)
#pragma unroll
                for (int ct = 0; ct < 4; ct++)
                    MMA_TF32(acc[rt][ct], a[rt][0], a[rt][1], a[rt][2], a[rt][3],
                             b[ct][0], b[ct][1]);
        }
        __syncthreads();
    }

    // frags -> Cs[64][264]
#pragma unroll
    for (int rt = 0; rt < 4; rt++)
#pragma unroll
        for (int ct = 0; ct < 4; ct++) {
            int r = rt * 16 + lr;
            int c = warp * 32 + ct * 8 + 2 * lc;
            Cs[r * 264 + c]           = acc[rt][ct][0];
            Cs[r * 264 + c + 1]       = acc[rt][ct][1];
            Cs[(r + 8) * 264 + c]     = acc[rt][ct][2];
            Cs[(r + 8) * 264 + c + 1] = acc[rt][ct][3];
        }
    __syncthreads();

    // LN pass: warp owns 8 rows; lane owns 8-col chunk c0 = lane*8
    const int c0 = lane * 8;
    float4 bb0 = *(const float4*)(bias + c0);
    float4 bb1 = *(const float4*)(bias + c0 + 4);
    float4 gg0 = *(const float4*)(gamma + c0);
    float4 gg1 = *(const float4*)(gamma + c0 + 4);
    float4 be0 = *(const float4*)(beta + c0);
    float4 be1 = *(const float4*)(beta + c0 + 4);
    const float bbv[8] = {bb0.x, bb0.y, bb0.z, bb0.w, bb1.x, bb1.y, bb1.z, bb1.w};
    const float ggv[8] = {gg0.x, gg0.y, gg0.z, gg0.w, gg1.x, gg1.y, gg1.z, gg1.w};
    const float bev[8] = {be0.x, be0.y, be0.z, be0.w, be1.x, be1.y, be1.z, be1.w};

#pragma unroll
    for (int i = 0; i < 8; i++) {
        int rloc = warp * 8 + i;
        int r = bm + rloc;
        const float* mrow = msa + (size_t)r * 256;
        float4 m0 = *(const float4*)(mrow + c0);
        float4 m1 = *(const float4*)(mrow + c0 + 4);
        const float mv[8] = {m0.x, m0.y, m0.z, m0.w, m1.x, m1.y, m1.z, m1.w};
        float4 cA = *(const float4*)(Cs + rloc * 264 + c0);
        float4 cB = *(const float4*)(Cs + rloc * 264 + c0 + 4);
        const float cv[8] = {cA.x, cA.y, cA.z, cA.w, cB.x, cB.y, cB.z, cB.w};
        float v[8], s = 0.f;
#pragma unroll
        for (int j = 0; j < 8; j++) {
            v[j] = cv[j] + bbv[j] + mv[j];
            s += v[j];
        }
#pragma unroll
        for (int off = 16; off > 0; off >>= 1)
            s += __shfl_xor_sync(0xffffffffu, s, off);
        float mu = s * (1.0f / 256.0f);
        float s2 = 0.f;
#pragma unroll
        for (int j = 0; j < 8; j++) {
            v[j] -= mu;
            s2 += v[j] * v[j];
        }
#pragma unroll
        for (int off = 16; off > 0; off >>= 1)
            s2 += __shfl_xor_sync(0xffffffffu, s2, off);
        float rs = rsqrtf(s2 * (1.0f / 256.0f) + EPS_F);
        float4 o0, o1;
        o0.x = v[0] * rs * ggv[0] + bev[0];
        o0.y = v[1] * rs * ggv[1] + bev[1];
        o0.z = v[2] * rs * ggv[2] + bev[2];
        o0.w = v[3] * rs * ggv[3] + bev[3];
        o1.x = v[4] * rs * ggv[4] + bev[4];
        o1.y = v[5] * rs * ggv[5] + bev[5];
        o1.z = v[6] * rs * ggv[6] + bev[6];
        o1.w = v[7] * rs * ggv[7] + bev[7];
        *(float4*)(out + (size_t)r * 256 + c0)     = o0;
        *(float4*)(out + (size_t)r * 256 + c0 + 4) = o1;
    }
}

// ---------------------------------------------------------------------------
extern "C" void kernel_launch(void* const* d_in, const int* in_sizes, int n_in,
                              void* d_out, int out_size) {
    const float* msa            = (const float*)d_in[0];
    const float* pair           = (const float*)d_in[1];
    const void*  mask_raw       = (const void*)d_in[2];
    const float* qkv_w          = (const float*)d_in[3];
    const float* qkv_b          = (const float*)d_in[4];
    const float* out_w          = (const float*)d_in[5];
    const float* out_b           = (const float*)d_in[6];
    const float* pb_w           = (const float*)d_in[7];
    const float* pb_b           = (const float*)d_in[8];
    const float* gamma          = (const float*)d_in[9];
    const float* beta           = (const float*)d_in[10];
    float* out = (float*)d_out;
    (void)in_sizes; (void)n_in; (void)out_size;

    cudaFuncSetAttribute(k_attn, cudaFuncAttributeMaxDynamicSharedMemorySize,
                         AT_SMEM_BYTES);
    cudaFuncSetAttribute(k_proj, cudaFuncAttributeMaxDynamicSharedMemorySize,
                         PROJ_SMEM_BYTES);

    k_mask<<<1, 256>>>(mask_raw);
    k_pair<<<2048, 256>>>(pair, pb_w, pb_b);
    k_qkv<<<dim3(12, 256), 256>>>(msa, qkv_w, qkv_b);
    k_attn<<<dim3(8, 128), 256, AT_SMEM_BYTES>>>();
    k_proj<<<512, 256, PROJ_SMEM_BYTES>>>(out_w, out_b, msa, gamma, beta, out);
}

// round 11
// speedup vs baseline: 2.2669x; 1.0812x over previous
#include <cuda_runtime.h>
#include <cstdint>

#define S_DIM 128
#define N_DIM 256
#define C_DIM 256
#define H_DIM 8
#define R_TOT (S_DIM * N_DIM)     // 32768 rows
#define QKV_K 768
#define SCALE_F 0.17677669529663687f
#define NEG_F  (-1000000000.0f)
#define EPS_F  1e-5f

// Scratch (allocation-free rule: __device__ globals)
__device__ float g_qkv[(size_t)R_TOT * QKV_K];          // 96 MB: fused q|k|v rows
__device__ float g_bias[(size_t)H_DIM * N_DIM * N_DIM]; // 2 MB: pair bias [h][n][m]
__device__ float g_att[(size_t)R_TOT * C_DIM];          // 32 MB: attention output
__device__ float g_maskf[S_DIM * N_DIM];                // canonical 0/1 mask

// ---------------------------------------------------------------------------
// tf32 helpers
// ---------------------------------------------------------------------------
__device__ __forceinline__ uint32_t f2tf32(float x) {
    uint32_t r; asm("cvt.rna.tf32.f32 %0, %1;" : "=r"(r) : "f"(x)); return r;
}
__device__ __forceinline__ float f2tf32f(float x) {
    return __uint_as_float(f2tf32(x));
}

#define MMA_TF32(c, a0, a1, a2, a3, b0, b1)                               \
    asm volatile("mma.sync.aligned.m16n8k8.row.col.f32.tf32.tf32.f32 "    \
                 "{%0,%1,%2,%3}, {%4,%5,%6,%7}, {%8,%9}, {%0,%1,%2,%3};"  \
                 : "+f"(c[0]), "+f"(c[1]), "+f"(c[2]), "+f"(c[3])         \
                 : "r"(a0), "r"(a1), "r"(a2), "r"(a3), "r"(b0), "r"(b1))

// ---------------------------------------------------------------------------
// Kernel 0: mask canonicalization, parallelized (32 blocks).
// Mode detection is recomputed redundantly per block (deterministic).
// ---------------------------------------------------------------------------
__global__ void k_mask(const void* __restrict__ mraw) {
    __shared__ int cnt[3];
    const unsigned char* b = (const unsigned char*)mraw;
    const int tid = threadIdx.x;
    if (tid < 3) cnt[tid] = 0;
    __syncthreads();
    int l0 = 0, l1 = 0, l23 = 0;
    for (int i = tid * 16; i < tid * 16 + 16; i++) {   // first 4096 bytes
        int nz = (b[i] != 0);
        int p = i & 3;
        if (p == 0) l0 += nz;
        else if (p == 1) l1 += nz;
        else l23 += nz;
    }
    atomicAdd(&cnt[0], l0);
    atomicAdd(&cnt[1], l1);
    atomicAdd(&cnt[2], l23);
    __syncthreads();
    int mode;
    if (cnt[1] > 0) mode = 0;             // uint8 bool
    else if (cnt[0] > 0) mode = 1;        // int32
    else mode = 2;                        // float32
    const int base = blockIdx.x * 1024;
    for (int i = base + tid; i < base + 1024; i += 256) {
        float v;
        if (mode == 0)      v = (float)b[i];
        else if (mode == 1) v = (float)((const int*)mraw)[i];
        else                v = ((const float*)mraw)[i];
        g_maskf[i] = (v != 0.0f) ? 1.0f : 0.0f;
    }
}

// ---------------------------------------------------------------------------
// Kernel 1: qkv = msa @ qkv_w^T + qkv_b via tf32 mma.sync.
// CTA tile 128(M)x64(N), 8 warps (2M x 4N), K-chunk 32.
// Register double-buffering: next tile's LDGs issue right after the
// post-store sync and are consumed after the post-mma sync.
// ---------------------------------------------------------------------------
__global__ void __launch_bounds__(256) k_qkv(const float* __restrict__ A,
                                             const float* __restrict__ W,
                                             const float* __restrict__ bias) {
    __shared__ float sm[8704];            // max(As+Bs = 6912, Cs = 8704)
    float* As = sm;                       // [128][36] tf32
    float* Bs = sm + 128 * 36;            // [64][36]  tf32
    float* Cs = sm;                       // epilogue  [128][68]
    const int tid = threadIdx.x, lane = tid & 31, warp = tid >> 5;
    const int lr = lane >> 2, lc = lane & 3;
    const int bm = blockIdx.y * 128, bn = blockIdx.x * 64;
    const int warpM = warp & 1, warpN = warp >> 1;

    // per-thread staging coordinates
    const int arow = tid >> 3, akc = (tid & 7) << 2;       // + j*32 rows
    const int brow = tid >> 3, bkc = (tid & 7) << 2;       // + j*32 rows (j<2)

    float cc[4][2][4];
#pragma unroll
    for (int rt = 0; rt < 4; rt++)
#pragma unroll
        for (int ct = 0; ct < 2; ct++)
#pragma unroll
            for (int i = 0; i < 4; i++) cc[rt][ct][i] = 0.f;

    const uint32_t* Asu = (const uint32_t*)As;
    const uint32_t* Bsu = (const uint32_t*)Bs;

    float4 pa[4], pb[2];
#pragma unroll
    for (int j = 0; j < 4; j++)
        pa[j] = *(const float4*)(A + (size_t)(bm + arow + j * 32) * 256 + akc);
#pragma unroll
    for (int j = 0; j < 2; j++)
        pb[j] = *(const float4*)(W + (size_t)(bn + brow + j * 32) * 256 + bkc);

    for (int it = 0; it < 8; it++) {
        // store prefetched regs -> smem (tf32 convert)
#pragma unroll
        for (int j = 0; j < 4; j++) {
            float4 t = {f2tf32f(pa[j].x), f2tf32f(pa[j].y),
                        f2tf32f(pa[j].z), f2tf32f(pa[j].w)};
            *(float4*)(As + (arow + j * 32) * 36 + akc) = t;
        }
#pragma unroll
        for (int j = 0; j < 2; j++) {
            float4 t = {f2tf32f(pb[j].x), f2tf32f(pb[j].y),
                        f2tf32f(pb[j].z), f2tf32f(pb[j].w)};
            *(float4*)(Bs + (brow + j * 32) * 36 + bkc) = t;
        }
        __syncthreads();

        // issue next tile's loads (latency hidden behind mma below)
        if (it < 7) {
            int kn = (it + 1) * 32;
#pragma unroll
            for (int j = 0; j < 4; j++)
                pa[j] = *(const float4*)(A + (size_t)(bm + arow + j * 32) * 256 + kn + akc);
#pragma unroll
            for (int j = 0; j < 2; j++)
                pb[j] = *(const float4*)(W + (size_t)(bn + brow + j * 32) * 256 + kn + bkc);
        }

#pragma unroll
        for (int kk = 0; kk < 4; kk++) {
            int k0 = kk * 8;
            uint32_t a[4][4];
#pragma unroll
            for (int rt = 0; rt < 4; rt++) {
                int r = warpM * 64 + rt * 16 + lr;
                a[rt][0] = Asu[r * 36 + k0 + lc];
                a[rt][1] = Asu[(r + 8) * 36 + k0 + lc];
                a[rt][2] = Asu[r * 36 + k0 + lc + 4];
                a[rt][3] = Asu[(r + 8) * 36 + k0 + lc + 4];
            }
            uint32_t b[2][2];
#pragma unroll
            for (int ct = 0; ct < 2; ct++) {
                int n = warpN * 16 + ct * 8 + lr;
                b[ct][0] = Bsu[n * 36 + k0 + lc];
                b[ct][1] = Bsu[n * 36 + k0 + lc + 4];
            }
#pragma unroll
            for (int rt = 0; rt < 4; rt++)
#pragma unroll
                for (int ct = 0; ct < 2; ct++)
                    MMA_TF32(cc[rt][ct], a[rt][0], a[rt][1], a[rt][2], a[rt][3],
                             b[ct][0], b[ct][1]);
        }
        __syncthreads();
    }

    // epilogue: frags -> Cs -> coalesced global store with bias
#pragma unroll
    for (int rt = 0; rt < 4; rt++)
#pragma unroll
        for (int ct = 0; ct < 2; ct++) {
            int r = warpM * 64 + rt * 16 + lr;
            int c = warpN * 16 + ct * 8 + 2 * lc;
            Cs[r * 68 + c]           = cc[rt][ct][0];
            Cs[r * 68 + c + 1]       = cc[rt][ct][1];
            Cs[(r + 8) * 68 + c]     = cc[rt][ct][2];
            Cs[(r + 8) * 68 + c + 1] = cc[rt][ct][3];
        }
    __syncthreads();
#pragma unroll
    for (int j = 0; j < 8; j++) {        // 128x64 = 2048 float4
        int idx = tid + j * 256;
        int row = idx >> 4, c4 = (idx & 15) << 2;
        float4 v  = *(const float4*)(Cs + row * 68 + c4);
        float4 bb = *(const float4*)(bias + bn + c4);
        v.x += bb.x; v.y += bb.y; v.z += bb.z; v.w += bb.w;
        *(float4*)(g_qkv + (size_t)(bm + row) * QKV_K + bn + c4) = v;
    }
}

// ---------------------------------------------------------------------------
// Kernel 2: pair bias.  bias[h][n][m] = dot(pair[n][m][:], pb_w[h][:]) + pb_b[h]
// ---------------------------------------------------------------------------
__global__ void __launch_bounds__(256) k_pair(const float* __restrict__ pair,
                                              const float* __restrict__ pw,
                                              const float* __restrict__ pb) {
    __shared__ float pr[32][128];
    __shared__ float ws[8 * 128];
    const int tid = threadIdx.x;
    const int rb = blockIdx.x * 32;

    ((float4*)ws)[tid] = ((const float4*)pw)[tid];
#pragma unroll
    for (int j = 0; j < 4; j++) {
        int chunk = tid + j * 256;
        int r = chunk >> 5, pc = (chunk & 31) << 2;
        *(float4*)&pr[r][pc] = *(const float4*)(pair + (size_t)(rb + r) * 128 + pc);
    }
    __syncthreads();

    const int r = tid >> 3, h = tid & 7;
    const float* wr = ws + h * 128;
    float s = 0.f;
#pragma unroll
    for (int p = 0; p < 128; p += 4) {
        float4 a = *(const float4*)&pr[r][p];
        float4 w = *(const float4*)(wr + p);
        s += a.x * w.x + a.y * w.y + a.z * w.z + a.w * w.w;
    }
    g_bias[(size_t)h * (N_DIM * N_DIM) + rb + r] = s + pb[h];
}

// ---------------------------------------------------------------------------
// Kernel 3: attention via tf32 mma. One CTA per (s,h).
// Round 9: Q-chunk register prefetch — LDG for chunk qc+1 issues right after
// the QK^T mma (hidden behind score-store + softmax + PV).
// ---------------------------------------------------------------------------
#define AT_SMEM_FLOATS (9216 + 8448 + 8448 + 1152 + 256 + 32)
#define AT_SMEM_BYTES  (AT_SMEM_FLOATS * 4)

__global__ void __launch_bounds__(256) k_attn() {
    extern __shared__ float smf[];
    float* ks   = smf;            // [256][36]  K, tf32
    float* vt   = ks + 9216;      // [32][264]  V^T, tf32
    float* sc2  = vt + 8448;      // [32][264]  scores / exp (exp stored tf32)
    float* qs   = sc2 + 8448;     // [32][36]   Q chunk, tf32
    float* mk   = qs + 1152;      // [256]
    float* invs = mk + 256;       // [32]

    const int h = blockIdx.x, s = blockIdx.y;
    const int tid = threadIdx.x, lane = tid & 31, warp = tid >> 5;
    const int lr = lane >> 2, lc = lane & 3;

    mk[tid] = g_maskf[s * 256 + tid];
    {   // stage K [m][d] and V^T [d][m]; m = tid
        const float* kb = g_qkv + (size_t)(s * 256 + tid) * QKV_K + 256 + h * 32;
        const float* vb = kb + 256;
#pragma unroll
        for (int d4 = 0; d4 < 8; d4++) {
            float4 kv = *(const float4*)(kb + d4 * 4);
            float4 vv = *(const float4*)(vb + d4 * 4);
            float4 kt4 = {f2tf32f(kv.x), f2tf32f(kv.y), f2tf32f(kv.z), f2tf32f(kv.w)};
            *(float4*)(ks + tid * 36 + d4 * 4) = kt4;
            vt[(d4 * 4 + 0) * 264 + tid] = f2tf32f(vv.x);
            vt[(d4 * 4 + 1) * 264 + tid] = f2tf32f(vv.y);
            vt[(d4 * 4 + 2) * 264 + tid] = f2tf32f(vv.z);
            vt[(d4 * 4 + 3) * 264 + tid] = f2tf32f(vv.w);
        }
    }

    const uint32_t* ksu = (const uint32_t*)ks;
    const uint32_t* qsu = (const uint32_t*)qs;
    const uint32_t* su  = (const uint32_t*)sc2;
    const uint32_t* vu  = (const uint32_t*)vt;

    // Q staging coordinates + prefetch of chunk 0
    const int qn = tid >> 3, qdc = (tid & 7) << 2;
    float4 qpre = *(const float4*)(g_qkv + (size_t)(s * 256 + qn) * QKV_K + h * 32 + qdc);
    __syncthreads();

    for (int qc = 0; qc < 8; qc++) {
        const int n0g = qc * 32;
        {   // store prefetched Q chunk [n][d]
            float4 t = {f2tf32f(qpre.x), f2tf32f(qpre.y), f2tf32f(qpre.z), f2tf32f(qpre.w)};
            *(float4*)(qs + qn * 36 + qdc) = t;
        }
        __syncthreads();

        // --- QK^T: warp owns m-strip [warp*32, warp*32+32) over all 32 queries
        float cc[2][4][4];
#pragma unroll
        for (int rt = 0; rt < 2; rt++)
#pragma unroll
            for (int ct = 0; ct < 4; ct++)
#pragma unroll
                for (int i = 0; i < 4; i++) cc[rt][ct][i] = 0.f;

#pragma unroll
        for (int kt = 0; kt < 4; kt++) {
            int k0 = kt * 8;
            uint32_t a[2][4];
#pragma unroll
            for (int rt = 0; rt < 2; rt++) {
                int r = rt * 16 + lr;
                a[rt][0] = qsu[r * 36 + k0 + lc];
                a[rt][1] = qsu[(r + 8) * 36 + k0 + lc];
                a[rt][2] = qsu[r * 36 + k0 + lc + 4];
                a[rt][3] = qsu[(r + 8) * 36 + k0 + lc + 4];
            }
#pragma unroll
            for (int ct = 0; ct < 4; ct++) {
                int m0 = warp * 32 + ct * 8;
                uint32_t b0 = ksu[(m0 + lr) * 36 + k0 + lc];
                uint32_t b1 = ksu[(m0 + lr) * 36 + k0 + lc + 4];
                MMA_TF32(cc[0][ct], a[0][0], a[0][1], a[0][2], a[0][3], b0, b1);
                MMA_TF32(cc[1][ct], a[1][0], a[1][1], a[1][2], a[1][3], b0, b1);
            }
        }

        // prefetch next chunk's Q (consumed after 2 syncs, next iteration)
        if (qc < 7)
            qpre = *(const float4*)(g_qkv + (size_t)(s * 256 + (qc + 1) * 32 + qn) * QKV_K + h * 32 + qdc);

        // store raw scores to sc2[n][m]
#pragma unroll
        for (int rt = 0; rt < 2; rt++)
#pragma unroll
            for (int ct = 0; ct < 4; ct++) {
                int r = rt * 16 + lr, c = warp * 32 + ct * 8 + 2 * lc;
                sc2[r * 264 + c]           = cc[rt][ct][0];
                sc2[r * 264 + c + 1]       = cc[rt][ct][1];
                sc2[(r + 8) * 264 + c]     = cc[rt][ct][2];
                sc2[(r + 8) * 264 + c + 1] = cc[rt][ct][3];
            }
        __syncthreads();

        // --- softmax: warp handles rows n = warp*4 .. warp*4+3, coalesced in m
#pragma unroll
        for (int rr = 0; rr < 4; rr++) {
            int n = warp * 4 + rr, gn = n0g + n;
            float mn = mk[gn];
            const float* brow = g_bias + ((size_t)h * 256 + gn) * 256;
            float x[8], mx = -3.4e38f;
#pragma unroll
            for (int j = 0; j < 8; j++) {
                int m = lane + j * 32;
                float v = sc2[n * 264 + m] * SCALE_F;
                if (mn * mk[m] < 0.5f) v = NEG_F;
                v += brow[m];
                x[j] = v;
                mx = fmaxf(mx, v);
            }
#pragma unroll
            for (int off = 16; off > 0; off >>= 1)
                mx = fmaxf(mx, __shfl_xor_sync(0xffffffffu, mx, off));
            float sum = 0.f;
#pragma unroll
            for (int j = 0; j < 8; j++) {
                float e = __expf(x[j] - mx);
                sum += e;
                sc2[n * 264 + lane + j * 32] = f2tf32f(e);
            }
#pragma unroll
            for (int off = 16; off > 0; off >>= 1)
                sum += __shfl_xor_sync(0xffffffffu, sum, off);
            if (lane == 0) invs[n] = 1.0f / sum;
        }
        __syncthreads();

        // --- PV: warp -> output tile (rt = warp&1 [16 rows n], ct = warp>>1 [8 cols d])
        {
            int rt = warp & 1, ct = warp >> 1;
            float o[4] = {0.f, 0.f, 0.f, 0.f};
#pragma unroll
            for (int km = 0; km < 32; km++) {
                int m0 = km * 8;
                uint32_t a0 = su[(rt * 16 + lr) * 264 + m0 + lc];
                uint32_t a1 = su[(rt * 16 + lr + 8) * 264 + m0 + lc];
                uint32_t a2 = su[(rt * 16 + lr) * 264 + m0 + lc + 4];
                uint32_t a3 = su[(rt * 16 + lr + 8) * 264 + m0 + lc + 4];
                uint32_t b0 = vu[(ct * 8 + lr) * 264 + m0 + lc];
                uint32_t b1 = vu[(ct * 8 + lr) * 264 + m0 + lc + 4];
                MMA_TF32(o, a0, a1, a2, a3, b0, b1);
            }
            int r = rt * 16 + lr, d0 = ct * 8 + 2 * lc;
            float i0 = invs[r], i1 = invs[r + 8];
            *(float2*)(g_att + (size_t)(s * 256 + n0g + r) * 256 + h * 32 + d0) =
                make_float2(o[0] * i0, o[1] * i0);
            *(float2*)(g_att + (size_t)(s * 256 + n0g + r + 8) * 256 + h * 32 + d0) =
                make_float2(o[2] * i1, o[3] * i1);
        }
        __syncthreads();
    }
}

// ---------------------------------------------------------------------------
// Kernel 4: out-proj + bias + residual + LayerNorm, fused, tf32 mma.
// (unchanged from Round 8 — ~55us)
// ---------------------------------------------------------------------------
#define PROJ_SMEM_FLOATS 16896           // max(As 2304 + Bs 9216, Cs 64*264)
#define PROJ_SMEM_BYTES  (PROJ_SMEM_FLOATS * 4)

__global__ void __launch_bounds__(256) k_proj(const float* __restrict__ W,
                                              const float* __restrict__ bias,
                                              const float* __restrict__ msa,
                                              const float* __restrict__ gamma,
                                              const float* __restrict__ beta,
                                              float* __restrict__ out) {
    extern __shared__ float psm[];
    float* As = psm;                 // [64][36]  tf32
    float* Bs = psm + 64 * 36;       // [256][36] tf32
    float* Cs = psm;                 // epilogue [64][264]
    const int tid = threadIdx.x, lane = tid & 31, warp = tid >> 5;
    const int lr = lane >> 2, lc = lane & 3;
    const int bm = blockIdx.x * 64;

    float acc[4][4][4];
#pragma unroll
    for (int rt = 0; rt < 4; rt++)
#pragma unroll
        for (int ct = 0; ct < 4; ct++)
#pragma unroll
            for (int i = 0; i < 4; i++) acc[rt][ct][i] = 0.f;

    const uint32_t* Asu = (const uint32_t*)As;
    const uint32_t* Bsu = (const uint32_t*)Bs;

    for (int kt0 = 0; kt0 < 256; kt0 += 32) {
#pragma unroll
        for (int j = 0; j < 2; j++) {    // A: 64x32 = 512 float4
            int idx = tid + j * 256;
            int row = idx >> 3, kc = (idx & 7) << 2;
            float4 v = *(const float4*)(g_att + (size_t)(bm + row) * 256 + kt0 + kc);
            float4 t = {f2tf32f(v.x), f2tf32f(v.y), f2tf32f(v.z), f2tf32f(v.w)};
            *(float4*)(As + row * 36 + kc) = t;
        }
#pragma unroll
        for (int j = 0; j < 8; j++) {    // W: 256x32 = 2048 float4
            int idx = tid + j * 256;
            int n = idx >> 3, kc = (idx & 7) << 2;
            float4 v = *(const float4*)(W + (size_t)n * 256 + kt0 + kc);
            float4 t = {f2tf32f(v.x), f2tf32f(v.y), f2tf32f(v.z), f2tf32f(v.w)};
            *(float4*)(Bs + n * 36 + kc) = t;
        }
        __syncthreads();

#pragma unroll
        for (int kk = 0; kk < 4; kk++) {
            int k0 = kk * 8;
            uint32_t a[4][4];
#pragma unroll
            for (int rt = 0; rt < 4; rt++) {
                int r = rt * 16 + lr;
                a[rt][0] = Asu[r * 36 + k0 + lc];
                a[rt][1] = Asu[(r + 8) * 36 + k0 + lc];
                a[rt][2] = Asu[r * 36 + k0 + lc + 4];
                a[rt][3] = Asu[(r + 8) * 36 + k0 + lc + 4];
            }
            uint32_t b[4][2];
#pragma unroll
            for (int ct = 0; ct < 4; ct++) {
                int n = warp * 32 + ct * 8 + lr;
                b[ct][0] = Bsu[n * 36 + k0 + lc];
                b[ct][1] = Bsu[n * 36 + k0 + lc + 4];
            }
#pragma unroll
            for (int rt = 0; rt < 4; rt++)
#pragma unroll
                for (int ct = 0; ct < 4; ct++)
                    MMA_TF32(acc[rt][ct], a[rt][0], a[rt][1], a[rt][2], a[rt][3],
                             b[ct][0], b[ct][1]);
        }
        __syncthreads();
    }

    // frags -> Cs[64][264]
#pragma unroll
    for (int rt = 0; rt < 4; rt++)
#pragma unroll
        for (int ct = 0; ct < 4; ct++) {
            int r = rt * 16 + lr;
            int c = warp * 32 + ct * 8 + 2 * lc;
            Cs[r * 264 + c]           = acc[rt][ct][0];
            Cs[r * 264 + c + 1]       = acc[rt][ct][1];
            Cs[(r + 8) * 264 + c]     = acc[rt][ct][2];
            Cs[(r + 8) * 264 + c + 1] = acc[rt][ct][3];
        }
    __syncthreads();

    // LN pass: warp owns 8 rows; lane owns 8-col chunk c0 = lane*8
    const int c0 = lane * 8;
    float4 bb0 = *(const float4*)(bias + c0);
    float4 bb1 = *(const float4*)(bias + c0 + 4);
    float4 gg0 = *(const float4*)(gamma + c0);
    float4 gg1 = *(const float4*)(gamma + c0 + 4);
    float4 be0 = *(const float4*)(beta + c0);
    float4 be1 = *(const float4*)(beta + c0 + 4);
    const float bbv[8] = {bb0.x, bb0.y, bb0.z, bb0.w, bb1.x, bb1.y, bb1.z, bb1.w};
    const float ggv[8] = {gg0.x, gg0.y, gg0.z, gg0.w, gg1.x, gg1.y, gg1.z, gg1.w};
    const float bev[8] = {be0.x, be0.y, be0.z, be0.w, be1.x, be1.y, be1.z, be1.w};

#pragma unroll
    for (int i = 0; i < 8; i++) {
        int rloc = warp * 8 + i;
        int r = bm + rloc;
        const float* mrow = msa + (size_t)r * 256;
        float4 m0 = *(const float4*)(mrow + c0);
        float4 m1 = *(const float4*)(mrow + c0 + 4);
        const float mv[8] = {m0.x, m0.y, m0.z, m0.w, m1.x, m1.y, m1.z, m1.w};
        float4 cA = *(const float4*)(Cs + rloc * 264 + c0);
        float4 cB = *(const float4*)(Cs + rloc * 264 + c0 + 4);
        const float cv[8] = {cA.x, cA.y, cA.z, cA.w, cB.x, cB.y, cB.z, cB.w};
        float v[8], s = 0.f;
#pragma unroll
        for (int j = 0; j < 8; j++) {
            v[j] = cv[j] + bbv[j] + mv[j];
            s += v[j];
        }
#pragma unroll
        for (int off = 16; off > 0; off >>= 1)
            s += __shfl_xor_sync(0xffffffffu, s, off);
        float mu = s * (1.0f / 256.0f);
        float s2 = 0.f;
#pragma unroll
        for (int j = 0; j < 8; j++) {
            v[j] -= mu;
            s2 += v[j] * v[j];
        }
#pragma unroll
        for (int off = 16; off > 0; off >>= 1)
            s2 += __shfl_xor_sync(0xffffffffu, s2, off);
        float rs = rsqrtf(s2 * (1.0f / 256.0f) + EPS_F);
        float4 o0, o1;
        o0.x = v[0] * rs * ggv[0] + bev[0];
        o0.y = v[1] * rs * ggv[1] + bev[1];
        o0.z = v[2] * rs * ggv[2] + bev[2];
        o0.w = v[3] * rs * ggv[3] + bev[3];
        o1.x = v[4] * rs * ggv[4] + bev[4];
        o1.y = v[5] * rs * ggv[5] + bev[5];
        o1.z = v[6] * rs * ggv[6] + bev[6];
        o1.w = v[7] * rs * ggv[7] + bev[7];
        *(float4*)(out + (size_t)r * 256 + c0)     = o0;
        *(float4*)(out + (size_t)r * 256 + c0 + 4) = o1;
    }
}

// ---------------------------------------------------------------------------
extern "C" void kernel_launch(void* const* d_in, const int* in_sizes, int n_in,
                              void* d_out, int out_size) {
    const float* msa            = (const float*)d_in[0];
    const float* pair           = (const float*)d_in[1];
    const void*  mask_raw       = (const void*)d_in[2];
    const float* qkv_w          = (const float*)d_in[3];
    const float* qkv_b          = (const float*)d_in[4];
    const float* out_w          = (const float*)d_in[5];
    const float* out_b          = (const float*)d_in[6];
    const float* pb_w           = (const float*)d_in[7];
    const float* pb_b           = (const float*)d_in[8];
    const float* gamma          = (const float*)d_in[9];
    const float* beta           = (const float*)d_in[10];
    float* out = (float*)d_out;
    (void)in_sizes; (void)n_in; (void)out_size;

    cudaFuncSetAttribute(k_attn, cudaFuncAttributeMaxDynamicSharedMemorySize,
                         AT_SMEM_BYTES);
    cudaFuncSetAttribute(k_proj, cudaFuncAttributeMaxDynamicSharedMemorySize,
                         PROJ_SMEM_BYTES);

    k_mask<<<32, 256>>>(mask_raw);
    k_pair<<<2048, 256>>>(pair, pb_w, pb_b);
    k_qkv<<<dim3(12, 256), 256>>>(msa, qkv_w, qkv_b);
    k_attn<<<dim3(8, 128), 256, AT_SMEM_BYTES>>>();
    k_proj<<<512, 256, PROJ_SMEM_BYTES>>>(out_w, out_b, msa, gamma, beta, out);
}